// round 16
// baseline (speedup 1.0000x reference)
#include <cuda_runtime.h>
#include <cuda_bf16.h>
#include <cstdint>
#include <math.h>

#define NCANDS 100000
#define BQ     1024
#define MROWS  101120

__device__ __nv_bfloat16 g_Xb [(size_t)MROWS * 128];
__device__ __nv_bfloat16 g_Hb [(size_t)MROWS * 512];
__device__ __nv_bfloat16 g_Cb [(size_t)MROWS * 512];
__device__ __nv_bfloat16 g_W1T[512 * 128];
__device__ __nv_bfloat16 g_W2T[(size_t)512 * 512];
__device__ float g_nrm [MROWS];
__device__ float g_logits[BQ * 10];
__device__ float g_chunks[BQ * 20];

__device__ __forceinline__ uint32_t smem_u32(const void* p) {
    uint32_t a;
    asm("{ .reg .u64 t; cvta.to.shared.u64 t, %1; cvt.u32.u64 %0, t; }" : "=r"(a) : "l"(p));
    return a;
}
__device__ __forceinline__ void cp16(uint32_t s, const void* g) {
    asm volatile("cp.async.cg.shared.global [%0], [%1], 16;" :: "r"(s), "l"(g));
}
__device__ __forceinline__ void ldsm_x4(uint32_t* r, uint32_t a) {
    asm volatile("ldmatrix.sync.aligned.m8n8.x4.shared.b16 {%0,%1,%2,%3}, [%4];"
        : "=r"(r[0]), "=r"(r[1]), "=r"(r[2]), "=r"(r[3]) : "r"(a));
}
__device__ __forceinline__ void ldsm_x2(uint32_t* r, uint32_t a) {
    asm volatile("ldmatrix.sync.aligned.m8n8.x2.shared.b16 {%0,%1}, [%2];"
        : "=r"(r[0]), "=r"(r[1]) : "r"(a));
}
__device__ __forceinline__ void mma16816(float* c, const uint32_t* a, const uint32_t* b) {
    asm volatile("mma.sync.aligned.m16n8k16.row.col.f32.bf16.bf16.f32 "
        "{%0,%1,%2,%3}, {%4,%5,%6,%7}, {%8,%9}, {%0,%1,%2,%3};"
        : "+f"(c[0]), "+f"(c[1]), "+f"(c[2]), "+f"(c[3])
        : "r"(a[0]), "r"(a[1]), "r"(a[2]), "r"(a[3]), "r"(b[0]), "r"(b[1]));
}
__device__ __forceinline__ uint32_t packbf(float lo, float hi) {
    uint32_t d;
    asm("cvt.rn.bf16x2.f32 %0, %1, %2;" : "=r"(d) : "f"(hi), "f"(lo));
    return d;
}

// pipelined GEMM: 128x128 CTA tile, 8 warps (2x4), 64x32 warp tile
#define STAGE_B 32768
__device__ __forceinline__ void issue_stage(const __nv_bfloat16* gA, int ldA,
    const __nv_bfloat16* gB, int ldB, int k0, uint32_t sbase, int stage, int tid)
{
    #pragma unroll
    for (int i = 0; i < 8; i++) {
        int o = tid + 256 * i;
        int isB = o >> 10, r = (o >> 3) & 127, seg = o & 7;
        const __nv_bfloat16* src =
            (isB ? gB + (size_t)r * ldB : gA + (size_t)r * ldA) + k0 + seg * 8;
        cp16(sbase + (uint32_t)(stage * STAGE_B + isB * 16384 + r * 128
                                + ((seg ^ (r & 7)) * 16)), src);
    }
    asm volatile("cp.async.commit_group;" ::: "memory");
}

__device__ __forceinline__ void ld_frags(uint32_t bA, uint32_t bB, int kp,
    int wm, int wn, int lane, uint32_t af[4][4], uint32_t bf[4][2])
{
    #pragma unroll
    for (int mt = 0; mt < 4; mt++) {
        int row = wm * 64 + mt * 16 + (lane & 15);
        int seg = kp * 2 + (lane >> 4);
        ldsm_x4(af[mt], bA + (uint32_t)(row * 128 + ((seg ^ (row & 7)) * 16)));
    }
    #pragma unroll
    for (int nb = 0; nb < 2; nb++) {
        int row = wn * 32 + nb * 16 + (lane & 7) + ((lane >> 4) & 1) * 8;
        int seg = kp * 2 + ((lane >> 3) & 1);
        uint32_t r4[4];
        ldsm_x4(r4, bB + (uint32_t)(row * 128 + ((seg ^ (row & 7)) * 16)));
        bf[nb*2][0]   = r4[0]; bf[nb*2][1]   = r4[1];
        bf[nb*2+1][0] = r4[2]; bf[nb*2+1][1] = r4[3];
    }
}

__device__ __forceinline__ void mma_stage(uint32_t sbase, int stage,
    int wm, int wn, int lane, float acc[4][4][4])
{
    uint32_t bA = sbase + stage * STAGE_B;
    uint32_t bB = bA + 16384;
    uint32_t af[2][4][4], bf[2][4][2];
    ld_frags(bA, bB, 0, wm, wn, lane, af[0], bf[0]);
    #pragma unroll
    for (int kp = 0; kp < 4; kp++) {
        if (kp < 3)
            ld_frags(bA, bB, kp + 1, wm, wn, lane, af[(kp + 1) & 1], bf[(kp + 1) & 1]);
        #pragma unroll
        for (int mt = 0; mt < 4; mt++)
            #pragma unroll
            for (int nt = 0; nt < 4; nt++)
                mma16816(acc[mt][nt], af[kp & 1][mt], bf[kp & 1][nt]);
    }
}

// pre = stages 0,1 already issued (cross-tile prefetch)
__device__ __forceinline__ void gemm_main(const __nv_bfloat16* gA, int ldA,
    const __nv_bfloat16* gB, int ldB, int kIters, uint32_t sbase,
    int tid, int wm, int wn, int lane, float acc[4][4][4], bool pre)
{
    if (!pre) {
        issue_stage(gA, ldA, gB, ldB, 0, sbase, 0, tid);
        if (kIters > 1) issue_stage(gA, ldA, gB, ldB, 64, sbase, 1, tid);
    }
    for (int ki = 0; ki < kIters; ki++) {
        if (ki + 1 < kIters) asm volatile("cp.async.wait_group 1;" ::: "memory");
        else                 asm volatile("cp.async.wait_group 0;" ::: "memory");
        __syncthreads();
        if (ki + 2 < kIters)
            issue_stage(gA, ldA, gB, ldB, (ki + 2) * 64, sbase, (ki + 2) % 3, tid);
        mma_stage(sbase, ki % 3, wm, wn, lane, acc);
    }
}

// prep: pack X, transpose weights, zero accumulators
__global__ void k_prep(const float* __restrict__ xn, const float* __restrict__ xc,
                       const float* __restrict__ cn, const float* __restrict__ cc,
                       const float* __restrict__ W1, const float* __restrict__ W2) {
    size_t i = (size_t)blockIdx.x * 256 + threadIdx.x;
    if (i < (size_t)MROWS * 128) {
        int r = (int)(i >> 7), c = (int)(i & 127);
        float v = 0.f;
        if (c < 96) {
            if (r < NCANDS)           v = (c < 64) ? cn[(size_t)r * 64 + c] : cc[(size_t)r * 32 + c - 64];
            else if (r < NCANDS + BQ) { int q = r - NCANDS;
                                        v = (c < 64) ? xn[(size_t)q * 64 + c] : xc[(size_t)q * 32 + c - 64]; }
        }
        g_Xb[i] = __float2bfloat16(v);
    }
    if (i < 512 * 128) {
        int n = (int)(i >> 7), k = (int)(i & 127);
        g_W1T[i] = __float2bfloat16(k < 96 ? W1[(size_t)k * 512 + n] : 0.f);
    }
    if (i < 512 * 512) {
        int n = (int)(i >> 9), k = (int)(i & 511);
        g_W2T[i] = __float2bfloat16(W2[(size_t)k * 512 + n]);
    }
    if (i < BQ * 10) g_logits[i] = 0.f;
    if (i < BQ * 20) g_chunks[i] = 0.f;
    if (i < MROWS)   g_nrm[i]    = 0.f;
}

// encoder, grid (4, 790), 256 threads
#define ENC_SMEM (3 * STAGE_B + 512)
template<bool RELU, bool NORM>
__global__ __launch_bounds__(256, 2)
void k_enc(const __nv_bfloat16* __restrict__ gA, int ldA, int kIters,
           const __nv_bfloat16* __restrict__ gW, const float* __restrict__ bias,
           __nv_bfloat16* __restrict__ gOut)
{
    extern __shared__ char smArr[];
    uint32_t sbase = smem_u32(smArr);
    float* biasS = (float*)(smArr + 3 * STAGE_B);
    int tid = threadIdx.x, lane = tid & 31, wid = tid >> 5;
    int wm = wid & 1, wn = wid >> 1;
    int m0 = blockIdx.y * 128, N0 = blockIdx.x * 128;
    if (tid < 128) biasS[tid] = bias[N0 + tid];

    float acc[4][4][4] = {};
    gemm_main(gA + (size_t)m0 * ldA, ldA, gW + (size_t)N0 * ldA, ldA,
              kIters, sbase, tid, wm, wn, lane, acc, false);

    int g = lane >> 2, cq = lane & 3;
    #pragma unroll
    for (int mt = 0; mt < 4; mt++) {
        int r0 = m0 + wm*64 + mt*16 + g, r1 = r0 + 8;
        float s0 = 0.f, s1 = 0.f;
        #pragma unroll
        for (int nt = 0; nt < 4; nt++) {
            int cl = wn*32 + nt*8 + cq*2;
            float b0 = biasS[cl], b1 = biasS[cl + 1];
            float v00 = acc[mt][nt][0] + b0, v01 = acc[mt][nt][1] + b1;
            float v10 = acc[mt][nt][2] + b0, v11 = acc[mt][nt][3] + b1;
            if (RELU) {
                v00 = fmaxf(v00, 0.f); v01 = fmaxf(v01, 0.f);
                v10 = fmaxf(v10, 0.f); v11 = fmaxf(v11, 0.f);
            }
            if (NORM) {
                s0 += v00 * v00 + v01 * v01;
                s1 += v10 * v10 + v11 * v11;
            }
            *(uint32_t*)(gOut + (size_t)r0 * 512 + N0 + cl) = packbf(v00, v01);
            *(uint32_t*)(gOut + (size_t)r1 * 512 + N0 + cl) = packbf(v10, v11);
        }
        if (NORM) {
            s0 += __shfl_xor_sync(0xffffffffu, s0, 1);
            s0 += __shfl_xor_sync(0xffffffffu, s0, 2);
            s1 += __shfl_xor_sync(0xffffffffu, s1, 1);
            s1 += __shfl_xor_sync(0xffffffffu, s1, 2);
            if (cq == 0) {
                atomicAdd(&g_nrm[r0], s0);
                atomicAdd(&g_nrm[r1], s1);
            }
        }
    }
}

// distance, grid (8, 391), 2 candidate tiles per CTA, 256 threads
#define Y_OFF   (3 * STAGE_B)
#define QN_OFF  (Y_OFF + 4352)
#define CN_OFF  (QN_OFF + 512)
#define CL_OFF  (CN_OFF + 512)
#define CH_OFF  (CL_OFF + 512)
#define DI_SMEM (CH_OFF + 1024)

__global__ __launch_bounds__(256, 2)
void k_dist(const int* __restrict__ cy)
{
    extern __shared__ char smArr[];
    uint32_t sbase = smem_u32(smArr);
    __nv_bfloat16* Ysm = (__nv_bfloat16*)(smArr + Y_OFF);
    float* qnS = (float*)(smArr + QN_OFF);
    float* cnS = (float*)(smArr + CN_OFF);
    int*   clS = (int*)(smArr + CL_OFF);
    float* chS = (float*)(smArr + CH_OFF);
    int tid = threadIdx.x, lane = tid & 31, wid = tid >> 5;
    int wm = wid & 1, wn = wid >> 1;
    int qt = blockIdx.x;
    int qbase = NCANDS + qt * 128;
    const __nv_bfloat16* Qp = g_Cb + (size_t)qbase * 512;

    if (tid < 128) qnS[tid] = g_nrm[qbase + tid];

    int g = lane >> 2, cq = lane & 3;

    #pragma unroll 1
    for (int t = 0; t < 2; t++) {
        int ct = (blockIdx.y << 1) | t;
        int n0 = ct * 128;
        int validN = min(NCANDS - n0, 128);
        int lo = n0 / 5000;
        int jb = min((lo + 1) * 5000 - n0, 128);
        const __nv_bfloat16* Bp = g_Cb + (size_t)n0 * 512;

        if (tid < 128) {
            cnS[tid] = g_nrm[n0 + tid];
            clS[tid] = (tid < validN) ? cy[n0 + tid] : 10;
        }
        chS[tid] = 0.f;
        for (int i = tid; i < 16 * 128; i += 256) {
            int n = i >> 7, k = i & 127;
            float v = (k < validN && n < 10 && cy[n0 + k] == n) ? 1.f : 0.f;
            Ysm[n * 136 + k] = __float2bfloat16(v);
        }
        __syncthreads();

        float acc[4][4][4] = {};
        gemm_main(Qp, 512, Bp, 512, 8, sbase, tid, wm, wn, lane, acc, t == 1);
        __syncthreads();

        // cross-tile prefetch: next tile's first 2 stages fill during epilogue
        if (t == 0) {
            const __nv_bfloat16* Bp2 = Bp + (size_t)128 * 512;
            issue_stage(Qp, 512, Bp2, 512, 0,  sbase, 0, tid);
            issue_stage(Qp, 512, Bp2, 512, 64, sbase, 1, tid);
        }

        // epilogue
        float qn0[4], qn1[4];
        #pragma unroll
        for (int mt = 0; mt < 4; mt++) {
            qn0[mt] = qnS[wm*64 + mt*16 + g];
            qn1[mt] = qnS[wm*64 + mt*16 + g + 8];
        }
        float cnv[8]; int clv[8]; bool sl0[8];
        #pragma unroll
        for (int nt = 0; nt < 4; nt++)
            #pragma unroll
            for (int h = 0; h < 2; h++) {
                int col = wn*32 + nt*8 + cq*2 + h;
                cnv[nt*2+h] = cnS[col]; clv[nt*2+h] = clS[col]; sl0[nt*2+h] = col < jb;
            }
        uint32_t bY[2][2][2];
        #pragma unroll
        for (int kc = 0; kc < 2; kc++)
            #pragma unroll
            for (int ng = 0; ng < 2; ng++) {
                uint32_t a = sbase + Y_OFF
                    + (uint32_t)((ng*8 + (lane & 7)) * 272
                                 + (wn*32 + kc*16 + ((lane >> 3) & 1) * 8) * 2);
                ldsm_x2(bY[kc][ng], a);
            }

        float D1[4][2][4] = {};
        float ch0[4][2] = {}, ch1[4][2] = {};
        #pragma unroll
        for (int mt = 0; mt < 4; mt++) {
            float ed[4][4];
            #pragma unroll
            for (int nt = 0; nt < 4; nt++)
                #pragma unroll
                for (int i = 0; i < 4; i++) {
                    int cidx = nt*2 + (i & 1);
                    float qn = (i < 2) ? qn0[mt] : qn1[mt];
                    float sq = fmaxf(qn + cnv[cidx] - 2.f * acc[mt][nt][i], 0.f);
                    float d; asm("sqrt.approx.f32 %0, %1;" : "=f"(d) : "f"(sq));
                    float e = __expf(-d);
                    ed[nt][i] = e;
                    float em = e * (1.f + e * (0.5f + e * (0.166666667f
                                  + e * (0.0416666667f + e * 0.00833333333f))));
                    if (clv[cidx] < 10) {
                        int gi = i >> 1;
                        if (sl0[cidx]) ch0[mt][gi] += em; else ch1[mt][gi] += em;
                    }
                }
            #pragma unroll
            for (int kc = 0; kc < 2; kc++) {
                uint32_t a[4] = { packbf(ed[2*kc][0],   ed[2*kc][1]),
                                  packbf(ed[2*kc][2],   ed[2*kc][3]),
                                  packbf(ed[2*kc+1][0], ed[2*kc+1][1]),
                                  packbf(ed[2*kc+1][2], ed[2*kc+1][3]) };
                mma16816(D1[mt][0], a, bY[kc][0]);
                mma16816(D1[mt][1], a, bY[kc][1]);
            }
        }
        #pragma unroll
        for (int mt = 0; mt < 4; mt++)
            #pragma unroll
            for (int gi = 0; gi < 2; gi++) {
                int row = wm*64 + mt*16 + g + gi*8;
                if (ch0[mt][gi] != 0.f) atomicAdd(&chS[row*2],     ch0[mt][gi]);
                if (ch1[mt][gi] != 0.f) atomicAdd(&chS[row*2 + 1], ch1[mt][gi]);
            }
        __syncthreads();

        // cross-warp reduce of D1 (over wn) in stage-2 smem region (not prefetched)
        float* red = (float*)(smArr + 2 * STAGE_B);
        #pragma unroll
        for (int mt = 0; mt < 4; mt++) {
            int r0 = wm*64 + mt*16 + g;
            #pragma unroll
            for (int ng = 0; ng < 2; ng++)
                #pragma unroll
                for (int j = 0; j < 4; j++) {
                    int col = ng*8 + cq*2 + (j & 1);
                    if (col < 10)
                        red[(wn*128 + r0 + (j >> 1)*8) * 12 + col] = D1[mt][ng][j];
                }
        }
        __syncthreads();
        for (int i = tid; i < 1280; i += 256) {
            int row = i / 10, col = i % 10;
            float v = red[row*12 + col] + red[(128 + row)*12 + col]
                    + red[(256 + row)*12 + col] + red[(384 + row)*12 + col];
            if (v != 0.f) atomicAdd(&g_logits[(qt*128 + row)*10 + col], v);
        }
        {
            int row = tid >> 1, s = tid & 1;
            float v = chS[tid];
            int c = lo + s;
            if (v != 0.f && c < 20) atomicAdd(&g_chunks[(qt*128 + row)*20 + c], v);
        }
        __syncthreads();
    }
}

__global__ __launch_bounds__(256)
void k_finalize(float* __restrict__ out) {
    int b = blockIdx.x * 256 + threadIdx.x;
    if (b >= BQ) return;
    float lse = 0.f;
    #pragma unroll
    for (int c = 0; c < 20; c++) lse += logf(5000.f + g_chunks[b * 20 + c]);
    #pragma unroll
    for (int k = 0; k < 10; k++)
        out[b * 10 + k] = logf(g_logits[b * 10 + k]) - lse;
}

extern "C" void kernel_launch(void* const* d_in, const int* in_sizes, int n_in,
                              void* d_out, int out_size)
{
    const float* x_num = (const float*)d_in[0];
    const float* x_cat = (const float*)d_in[1];
    const float* c_num = (const float*)d_in[2];
    const float* c_cat = (const float*)d_in[3];
    const int*   c_y   = (const int*)d_in[4];
    const float* W1    = (const float*)d_in[5];
    const float* b1    = (const float*)d_in[6];
    const float* W2    = (const float*)d_in[7];
    const float* b2    = (const float*)d_in[8];
    float* out = (float*)d_out;

    cudaFuncSetAttribute(k_enc<true,false>,  cudaFuncAttributeMaxDynamicSharedMemorySize, ENC_SMEM);
    cudaFuncSetAttribute(k_enc<false,true>,  cudaFuncAttributeMaxDynamicSharedMemorySize, ENC_SMEM);
    cudaFuncSetAttribute(k_dist,             cudaFuncAttributeMaxDynamicSharedMemorySize, DI_SMEM);

    __nv_bfloat16 *pXb, *pHb, *pCb, *pW1T, *pW2T;
    cudaGetSymbolAddress((void**)&pXb,  g_Xb);
    cudaGetSymbolAddress((void**)&pHb,  g_Hb);
    cudaGetSymbolAddress((void**)&pCb,  g_Cb);
    cudaGetSymbolAddress((void**)&pW1T, g_W1T);
    cudaGetSymbolAddress((void**)&pW2T, g_W2T);

    k_prep<<<(unsigned)(((size_t)MROWS * 128 + 255) / 256), 256>>>(
        x_num, x_cat, c_num, c_cat, W1, W2);
    k_enc<true,false ><<<dim3(4, 790), 256, ENC_SMEM>>>(pXb, 128, 2, pW1T, b1, pHb);
    k_enc<false,true ><<<dim3(4, 790), 256, ENC_SMEM>>>(pHb, 512, 8, pW2T, b2, pCb);
    k_dist<<<dim3(8, 391), 256, DI_SMEM>>>(c_y);
    k_finalize<<<4, 256>>>(out);
}

// round 17
// speedup vs baseline: 1.1019x; 1.1019x over previous
#include <cuda_runtime.h>
#include <cuda_bf16.h>
#include <cstdint>
#include <math.h>

#define NCANDS 100000
#define BQ     1024
#define MROWS  101120
#define CT782  782

__device__ __nv_bfloat16 g_Xb [(size_t)MROWS * 128];
__device__ __nv_bfloat16 g_Hb [(size_t)MROWS * 512];
__device__ __nv_bfloat16 g_Cb [(size_t)MROWS * 512];
__device__ __nv_bfloat16 g_W1T[512 * 128];
__device__ __nv_bfloat16 g_W2T[(size_t)512 * 512];
__device__ float g_nrm [MROWS];
__device__ float g_logits[BQ * 10];
__device__ float g_chunks[BQ * 20];

__device__ __forceinline__ uint32_t smem_u32(const void* p) {
    uint32_t a;
    asm("{ .reg .u64 t; cvta.to.shared.u64 t, %1; cvt.u32.u64 %0, t; }" : "=r"(a) : "l"(p));
    return a;
}
__device__ __forceinline__ void cp16(uint32_t s, const void* g) {
    asm volatile("cp.async.cg.shared.global [%0], [%1], 16;" :: "r"(s), "l"(g));
}
__device__ __forceinline__ void ldsm_x4(uint32_t* r, uint32_t a) {
    asm volatile("ldmatrix.sync.aligned.m8n8.x4.shared.b16 {%0,%1,%2,%3}, [%4];"
        : "=r"(r[0]), "=r"(r[1]), "=r"(r[2]), "=r"(r[3]) : "r"(a));
}
__device__ __forceinline__ void ldsm_x2(uint32_t* r, uint32_t a) {
    asm volatile("ldmatrix.sync.aligned.m8n8.x2.shared.b16 {%0,%1}, [%2];"
        : "=r"(r[0]), "=r"(r[1]) : "r"(a));
}
__device__ __forceinline__ void mma16816(float* c, const uint32_t* a, const uint32_t* b) {
    asm volatile("mma.sync.aligned.m16n8k16.row.col.f32.bf16.bf16.f32 "
        "{%0,%1,%2,%3}, {%4,%5,%6,%7}, {%8,%9}, {%0,%1,%2,%3};"
        : "+f"(c[0]), "+f"(c[1]), "+f"(c[2]), "+f"(c[3])
        : "r"(a[0]), "r"(a[1]), "r"(a[2]), "r"(a[3]), "r"(b[0]), "r"(b[1]));
}
__device__ __forceinline__ uint32_t packbf(float lo, float hi) {
    uint32_t d;
    asm("cvt.rn.bf16x2.f32 %0, %1, %2;" : "=r"(d) : "f"(hi), "f"(lo));
    return d;
}

// pipelined GEMM: 128x128 CTA tile, 8 warps (2x4), 64x32 warp tile
// K-stage 64, 3 stages, 128B-row XOR-swizzled smem, 256 threads.
#define STAGE_B 32768
__device__ __forceinline__ void issue_stage(const __nv_bfloat16* gA, int ldA,
    const __nv_bfloat16* gB, int ldB, int k0, uint32_t sbase, int stage, int tid)
{
    #pragma unroll
    for (int i = 0; i < 8; i++) {
        int o = tid + 256 * i;
        int isB = o >> 10, r = (o >> 3) & 127, seg = o & 7;
        const __nv_bfloat16* src =
            (isB ? gB + (size_t)r * ldB : gA + (size_t)r * ldA) + k0 + seg * 8;
        cp16(sbase + (uint32_t)(stage * STAGE_B + isB * 16384 + r * 128
                                + ((seg ^ (r & 7)) * 16)), src);
    }
    asm volatile("cp.async.commit_group;" ::: "memory");
}

__device__ __forceinline__ void ld_frags(uint32_t bA, uint32_t bB, int kp,
    int wm, int wn, int lane, uint32_t af[4][4], uint32_t bf[4][2])
{
    #pragma unroll
    for (int mt = 0; mt < 4; mt++) {
        int row = wm * 64 + mt * 16 + (lane & 15);
        int seg = kp * 2 + (lane >> 4);
        ldsm_x4(af[mt], bA + (uint32_t)(row * 128 + ((seg ^ (row & 7)) * 16)));
    }
    #pragma unroll
    for (int nb = 0; nb < 2; nb++) {
        int row = wn * 32 + nb * 16 + (lane & 7) + ((lane >> 4) & 1) * 8;
        int seg = kp * 2 + ((lane >> 3) & 1);
        uint32_t r4[4];
        ldsm_x4(r4, bB + (uint32_t)(row * 128 + ((seg ^ (row & 7)) * 16)));
        bf[nb*2][0]   = r4[0]; bf[nb*2][1]   = r4[1];
        bf[nb*2+1][0] = r4[2]; bf[nb*2+1][1] = r4[3];
    }
}

__device__ __forceinline__ void mma_stage(uint32_t sbase, int stage,
    int wm, int wn, int lane, float acc[4][4][4])
{
    uint32_t bA = sbase + stage * STAGE_B;
    uint32_t bB = bA + 16384;
    uint32_t af[2][4][4], bf[2][4][2];
    ld_frags(bA, bB, 0, wm, wn, lane, af[0], bf[0]);
    #pragma unroll
    for (int kp = 0; kp < 4; kp++) {
        if (kp < 3)
            ld_frags(bA, bB, kp + 1, wm, wn, lane, af[(kp + 1) & 1], bf[(kp + 1) & 1]);
        #pragma unroll
        for (int mt = 0; mt < 4; mt++)
            #pragma unroll
            for (int nt = 0; nt < 4; nt++)
                mma16816(acc[mt][nt], af[kp & 1][mt], bf[kp & 1][nt]);
    }
}

// fully-unrolled k-loop: stage indices are compile-time constants
template<int KITERS>
__device__ __forceinline__ void gemm_main(const __nv_bfloat16* gA, int ldA,
    const __nv_bfloat16* gB, int ldB, uint32_t sbase,
    int tid, int wm, int wn, int lane, float acc[4][4][4])
{
    issue_stage(gA, ldA, gB, ldB, 0, sbase, 0, tid);
    if (KITERS > 1) issue_stage(gA, ldA, gB, ldB, 64, sbase, 1, tid);
    #pragma unroll
    for (int ki = 0; ki < KITERS; ki++) {
        if (ki + 1 < KITERS) asm volatile("cp.async.wait_group 1;" ::: "memory");
        else                 asm volatile("cp.async.wait_group 0;" ::: "memory");
        __syncthreads();
        if (ki + 2 < KITERS)
            issue_stage(gA, ldA, gB, ldB, (ki + 2) * 64, sbase, (ki + 2) % 3, tid);
        mma_stage(sbase, ki % 3, wm, wn, lane, acc);
    }
}

// prep: pack X, transpose weights, zero accumulators
__global__ void k_prep(const float* __restrict__ xn, const float* __restrict__ xc,
                       const float* __restrict__ cn, const float* __restrict__ cc,
                       const float* __restrict__ W1, const float* __restrict__ W2) {
    size_t i = (size_t)blockIdx.x * 256 + threadIdx.x;
    if (i < (size_t)MROWS * 128) {
        int r = (int)(i >> 7), c = (int)(i & 127);
        float v = 0.f;
        if (c < 96) {
            if (r < NCANDS)           v = (c < 64) ? cn[(size_t)r * 64 + c] : cc[(size_t)r * 32 + c - 64];
            else if (r < NCANDS + BQ) { int q = r - NCANDS;
                                        v = (c < 64) ? xn[(size_t)q * 64 + c] : xc[(size_t)q * 32 + c - 64]; }
        }
        g_Xb[i] = __float2bfloat16(v);
    }
    if (i < 512 * 128) {
        int n = (int)(i >> 7), k = (int)(i & 127);
        g_W1T[i] = __float2bfloat16(k < 96 ? W1[(size_t)k * 512 + n] : 0.f);
    }
    if (i < 512 * 512) {
        int n = (int)(i >> 9), k = (int)(i & 511);
        g_W2T[i] = __float2bfloat16(W2[(size_t)k * 512 + n]);
    }
    if (i < BQ * 10) g_logits[i] = 0.f;
    if (i < BQ * 20) g_chunks[i] = 0.f;
    if (i < MROWS)   g_nrm[i]    = 0.f;
}

// encoder, grid (4, 790), 256 threads
#define ENC_SMEM (3 * STAGE_B + 512)
template<bool RELU, bool NORM, int KITERS>
__global__ __launch_bounds__(256, 2)
void k_enc(const __nv_bfloat16* __restrict__ gA, int ldA,
           const __nv_bfloat16* __restrict__ gW, const float* __restrict__ bias,
           __nv_bfloat16* __restrict__ gOut)
{
    extern __shared__ char smArr[];
    uint32_t sbase = smem_u32(smArr);
    float* biasS = (float*)(smArr + 3 * STAGE_B);
    int tid = threadIdx.x, lane = tid & 31, wid = tid >> 5;
    int wm = wid & 1, wn = wid >> 1;
    int m0 = blockIdx.y * 128, N0 = blockIdx.x * 128;
    if (tid < 128) biasS[tid] = bias[N0 + tid];

    float acc[4][4][4] = {};
    gemm_main<KITERS>(gA + (size_t)m0 * ldA, ldA, gW + (size_t)N0 * ldA, ldA,
                      sbase, tid, wm, wn, lane, acc);

    int g = lane >> 2, cq = lane & 3;
    #pragma unroll
    for (int mt = 0; mt < 4; mt++) {
        int r0 = m0 + wm*64 + mt*16 + g, r1 = r0 + 8;
        float s0 = 0.f, s1 = 0.f;
        #pragma unroll
        for (int nt = 0; nt < 4; nt++) {
            int cl = wn*32 + nt*8 + cq*2;
            float b0 = biasS[cl], b1 = biasS[cl + 1];
            float v00 = acc[mt][nt][0] + b0, v01 = acc[mt][nt][1] + b1;
            float v10 = acc[mt][nt][2] + b0, v11 = acc[mt][nt][3] + b1;
            if (RELU) {
                v00 = fmaxf(v00, 0.f); v01 = fmaxf(v01, 0.f);
                v10 = fmaxf(v10, 0.f); v11 = fmaxf(v11, 0.f);
            }
            if (NORM) {
                s0 += v00 * v00 + v01 * v01;
                s1 += v10 * v10 + v11 * v11;
            }
            *(uint32_t*)(gOut + (size_t)r0 * 512 + N0 + cl) = packbf(v00, v01);
            *(uint32_t*)(gOut + (size_t)r1 * 512 + N0 + cl) = packbf(v10, v11);
        }
        if (NORM) {
            s0 += __shfl_xor_sync(0xffffffffu, s0, 1);
            s0 += __shfl_xor_sync(0xffffffffu, s0, 2);
            s1 += __shfl_xor_sync(0xffffffffu, s1, 1);
            s1 += __shfl_xor_sync(0xffffffffu, s1, 2);
            if (cq == 0) {
                atomicAdd(&g_nrm[r0], s0);
                atomicAdd(&g_nrm[r1], s1);
            }
        }
    }
}

// distance, grid (8, 782), 256 threads
#define Y_OFF   (3 * STAGE_B)
#define QN_OFF  (Y_OFF + 4352)
#define CN_OFF  (QN_OFF + 512)
#define CL_OFF  (CN_OFF + 512)
#define CH_OFF  (CL_OFF + 512)
#define DI_SMEM (CH_OFF + 1024)

__global__ __launch_bounds__(256, 2)
void k_dist(const int* __restrict__ cy)
{
    extern __shared__ char smArr[];
    uint32_t sbase = smem_u32(smArr);
    __nv_bfloat16* Ysm = (__nv_bfloat16*)(smArr + Y_OFF);
    float* qnS = (float*)(smArr + QN_OFF);
    float* cnS = (float*)(smArr + CN_OFF);
    int*   clS = (int*)(smArr + CL_OFF);
    float* chS = (float*)(smArr + CH_OFF);
    int tid = threadIdx.x, lane = tid & 31, wid = tid >> 5;
    int wm = wid & 1, wn = wid >> 1;
    int qt = blockIdx.x, ct = blockIdx.y;
    int n0 = ct * 128, qbase = NCANDS + qt * 128;
    int validN = min(NCANDS - n0, 128);
    int lo = n0 / 5000;
    int jb = min((lo + 1) * 5000 - n0, 128);

    if (tid < 128) {
        qnS[tid] = g_nrm[qbase + tid];
        cnS[tid] = g_nrm[n0 + tid];
        clS[tid] = (tid < validN) ? cy[n0 + tid] : 10;
    }
    chS[tid] = 0.f;
    for (int i = tid; i < 16 * 128; i += 256) {
        int n = i >> 7, k = i & 127;
        float v = (k < validN && n < 10 && cy[n0 + k] == n) ? 1.f : 0.f;
        Ysm[n * 136 + k] = __float2bfloat16(v);
    }

    float acc[4][4][4] = {};
    gemm_main<8>(g_Cb + (size_t)qbase * 512, 512, g_Cb + (size_t)n0 * 512, 512,
                 sbase, tid, wm, wn, lane, acc);

    // epilogue
    int g = lane >> 2, cq = lane & 3;
    float qn0[4], qn1[4];
    #pragma unroll
    for (int mt = 0; mt < 4; mt++) {
        qn0[mt] = qnS[wm*64 + mt*16 + g];
        qn1[mt] = qnS[wm*64 + mt*16 + g + 8];
    }
    float cnv[8]; int clv[8]; bool sl0[8];
    #pragma unroll
    for (int nt = 0; nt < 4; nt++)
        #pragma unroll
        for (int h = 0; h < 2; h++) {
            int col = wn*32 + nt*8 + cq*2 + h;
            cnv[nt*2+h] = cnS[col]; clv[nt*2+h] = clS[col]; sl0[nt*2+h] = col < jb;
        }
    uint32_t bY[2][2][2];
    #pragma unroll
    for (int kc = 0; kc < 2; kc++)
        #pragma unroll
        for (int ng = 0; ng < 2; ng++) {
            uint32_t a = sbase + Y_OFF
                + (uint32_t)((ng*8 + (lane & 7)) * 272
                             + (wn*32 + kc*16 + ((lane >> 3) & 1) * 8) * 2);
            ldsm_x2(bY[kc][ng], a);
        }

    float D1[4][2][4] = {};
    float ch0[4][2] = {}, ch1[4][2] = {};
    #pragma unroll
    for (int mt = 0; mt < 4; mt++) {
        float ed[4][4];
        #pragma unroll
        for (int nt = 0; nt < 4; nt++)
            #pragma unroll
            for (int i = 0; i < 4; i++) {
                int cidx = nt*2 + (i & 1);
                float qn = (i < 2) ? qn0[mt] : qn1[mt];
                float sq = fmaxf(qn + cnv[cidx] - 2.f * acc[mt][nt][i], 0.f);
                float d; asm("sqrt.approx.f32 %0, %1;" : "=f"(d) : "f"(sq));
                float e = __expf(-d);
                ed[nt][i] = e;
                float em = e * (1.f + e * (0.5f + e * (0.166666667f
                              + e * (0.0416666667f + e * 0.00833333333f))));
                if (clv[cidx] < 10) {
                    int gi = i >> 1;
                    if (sl0[cidx]) ch0[mt][gi] += em; else ch1[mt][gi] += em;
                }
            }
        #pragma unroll
        for (int kc = 0; kc < 2; kc++) {
            uint32_t a[4] = { packbf(ed[2*kc][0],   ed[2*kc][1]),
                              packbf(ed[2*kc][2],   ed[2*kc][3]),
                              packbf(ed[2*kc+1][0], ed[2*kc+1][1]),
                              packbf(ed[2*kc+1][2], ed[2*kc+1][3]) };
            mma16816(D1[mt][0], a, bY[kc][0]);
            mma16816(D1[mt][1], a, bY[kc][1]);
        }
    }
    #pragma unroll
    for (int mt = 0; mt < 4; mt++)
        #pragma unroll
        for (int gi = 0; gi < 2; gi++) {
            int row = wm*64 + mt*16 + g + gi*8;
            if (ch0[mt][gi] != 0.f) atomicAdd(&chS[row*2],     ch0[mt][gi]);
            if (ch1[mt][gi] != 0.f) atomicAdd(&chS[row*2 + 1], ch1[mt][gi]);
        }
    __syncthreads();

    // cross-warp reduce of D1 (over wn) in stage smem
    float* red = (float*)smArr;
    #pragma unroll
    for (int mt = 0; mt < 4; mt++) {
        int r0 = wm*64 + mt*16 + g;
        #pragma unroll
        for (int ng = 0; ng < 2; ng++)
            #pragma unroll
            for (int j = 0; j < 4; j++) {
                int col = ng*8 + cq*2 + (j & 1);
                if (col < 10)
                    red[(wn*128 + r0 + (j >> 1)*8) * 12 + col] = D1[mt][ng][j];
            }
    }
    __syncthreads();
    for (int i = tid; i < 1280; i += 256) {
        int row = i / 10, col = i % 10;
        float v = red[row*12 + col] + red[(128 + row)*12 + col]
                + red[(256 + row)*12 + col] + red[(384 + row)*12 + col];
        if (v != 0.f) atomicAdd(&g_logits[(qt*128 + row)*10 + col], v);
    }
    {
        int row = tid >> 1, s = tid & 1;
        float v = chS[tid];
        int c = lo + s;
        if (v != 0.f && c < 20) atomicAdd(&g_chunks[(qt*128 + row)*20 + c], v);
    }
}

__global__ __launch_bounds__(256)
void k_finalize(float* __restrict__ out) {
    int b = blockIdx.x * 256 + threadIdx.x;
    if (b >= BQ) return;
    float lse = 0.f;
    #pragma unroll
    for (int c = 0; c < 20; c++) lse += logf(5000.f + g_chunks[b * 20 + c]);
    #pragma unroll
    for (int k = 0; k < 10; k++)
        out[b * 10 + k] = logf(g_logits[b * 10 + k]) - lse;
}

extern "C" void kernel_launch(void* const* d_in, const int* in_sizes, int n_in,
                              void* d_out, int out_size)
{
    const float* x_num = (const float*)d_in[0];
    const float* x_cat = (const float*)d_in[1];
    const float* c_num = (const float*)d_in[2];
    const float* c_cat = (const float*)d_in[3];
    const int*   c_y   = (const int*)d_in[4];
    const float* W1    = (const float*)d_in[5];
    const float* b1    = (const float*)d_in[6];
    const float* W2    = (const float*)d_in[7];
    const float* b2    = (const float*)d_in[8];
    float* out = (float*)d_out;

    cudaFuncSetAttribute(k_enc<true,false,2>, cudaFuncAttributeMaxDynamicSharedMemorySize, ENC_SMEM);
    cudaFuncSetAttribute(k_enc<false,true,8>, cudaFuncAttributeMaxDynamicSharedMemorySize, ENC_SMEM);
    cudaFuncSetAttribute(k_dist,              cudaFuncAttributeMaxDynamicSharedMemorySize, DI_SMEM);

    __nv_bfloat16 *pXb, *pHb, *pCb, *pW1T, *pW2T;
    cudaGetSymbolAddress((void**)&pXb,  g_Xb);
    cudaGetSymbolAddress((void**)&pHb,  g_Hb);
    cudaGetSymbolAddress((void**)&pCb,  g_Cb);
    cudaGetSymbolAddress((void**)&pW1T, g_W1T);
    cudaGetSymbolAddress((void**)&pW2T, g_W2T);

    k_prep<<<(unsigned)(((size_t)MROWS * 128 + 255) / 256), 256>>>(
        x_num, x_cat, c_num, c_cat, W1, W2);
    k_enc<true,false,2><<<dim3(4, 790), 256, ENC_SMEM>>>(pXb, 128, pW1T, b1, pHb);
    k_enc<false,true,8><<<dim3(4, 790), 256, ENC_SMEM>>>(pHb, 512, pW2T, b2, pCb);
    k_dist<<<dim3(8, CT782), 256, DI_SMEM>>>(c_y);
    k_finalize<<<4, 256>>>(out);
}